// round 12
// baseline (speedup 1.0000x reference)
#include <cuda_runtime.h>
#include <cuda_fp16.h>
#include <cstdint>
#include <cstddef>

#define N_NODES 12288
#define F 128
#define BM 128
#define BK 64
#define KSPLIT 12
#define KLEN (N_NODES / KSPLIT)     // 1024
#define KSTAGES (KLEN / BK)         // 16
#define TILES_M (N_NODES / BM)      // 96
#define GRID (TILES_M * KSPLIT)     // 1152
#define THREADS 512

#define A_BYTES (BM * 128)          // 16384 per A plane
#define ST_A2   (2 * A_BYTES)       // 32768: [sign][edge]
#define B_BYTES (128 * 128)         // 16384
#define STAGE_BYTES (ST_A2 + B_BYTES)   // 49152
#define SMEM_TOTAL  (2 * STAGE_BYTES)   // 98304

#define PLANE ((size_t)N_NODES * F)
#define SLICE (2 * PLANE)

// Scratch: 12 k-slices x [sign, edge] partial planes, fp16 featsT tiles, folded W
__device__ float g_S[(size_t)KSPLIT * 2 * N_NODES * F];   // ~151 MB
__device__ uint4 g_fB[(size_t)(N_NODES / BK) * B_BYTES / 16];
__device__ float g_cpart[96 * F];
__device__ float g_Wd[F * F];
__device__ float g_b2[F];

// ---------------------------------------------------------------------------
// helpers
// ---------------------------------------------------------------------------
__device__ __forceinline__ uint32_t smem_u32(const void* p) {
    uint32_t a;
    asm("{ .reg .u64 t; cvta.to.shared.u64 t, %1; cvt.u32.u64 %0, t; }"
        : "=r"(a) : "l"(p));
    return a;
}

__device__ __forceinline__ uint32_t pack_h2(float lo, float hi) {
    __half2 h = __floats2half2_rn(lo, hi);
    return *(uint32_t*)&h;
}

__device__ __forceinline__ float sgnf(float v) {
    return (v > 0.f ? 1.f : 0.f) - (v < 0.f ? 1.f : 0.f);
}

#define SWX(off) ((off) ^ (((off) >> 3) & 0x70))

#define CP_ASYNC16(dst_u32, src) \
    asm volatile("cp.async.cg.shared.global [%0], [%1], 16;" \
                 :: "r"(dst_u32), "l"(src) : "memory")
#define CP_COMMIT() asm volatile("cp.async.commit_group;" ::: "memory")
#define CP_WAIT0()  asm volatile("cp.async.wait_group 0;" ::: "memory")

#define LDSM_X4(r0, r1, r2, r3, addr) \
    asm volatile("ldmatrix.sync.aligned.m8n8.x4.shared.b16 {%0,%1,%2,%3}, [%4];" \
                 : "=r"(r0), "=r"(r1), "=r"(r2), "=r"(r3) : "r"(addr))

__device__ __forceinline__ void mma_f16(float* d, const uint32_t* a,
                                        uint32_t b0, uint32_t b1) {
    asm volatile(
        "mma.sync.aligned.m16n8k16.row.col.f32.f16.f16.f32 "
        "{%0,%1,%2,%3}, {%4,%5,%6,%7}, {%8,%9}, {%0,%1,%2,%3};\n"
        : "+f"(d[0]), "+f"(d[1]), "+f"(d[2]), "+f"(d[3])
        : "r"(a[0]), "r"(a[1]), "r"(a[2]), "r"(a[3]), "r"(b0), "r"(b1));
}

// ---------------------------------------------------------------------------
// Prepass kernels
// ---------------------------------------------------------------------------
__global__ __launch_bounds__(128)
void colsum_kernel(const float* __restrict__ feats) {
    const int t = threadIdx.x;
    const int r0 = blockIdx.x * 128;
    float s = 0.f;
#pragma unroll 4
    for (int r = 0; r < 128; ++r)
        s += feats[(size_t)(r0 + r) * F + t];
    g_cpart[blockIdx.x * F + t] = s;
}

__global__ __launch_bounds__(128)
void wtrans_kernel(const float* __restrict__ node_weight,
                   const float* __restrict__ node_bias) {
    __shared__ float cs[F];
    const int j = threadIdx.x;
    {
        float c = 0.f;
#pragma unroll 4
        for (int b = 0; b < 96; ++b)
            c += g_cpart[b * F + j];
        cs[j] = c;
    }
    __syncthreads();
    float b = node_bias[j];
#pragma unroll 4
    for (int k = 0; k < 128; ++k) {
        const float wt = node_weight[(size_t)k * F + j];
        const float wb = node_weight[(size_t)(k + 128) * F + j];
        g_Wd[k * F + j] = 0.5f * (wt - wb);
        b += cs[k] * 0.5f * (wt + wb);
    }
    g_b2[j] = b;
}

__global__ __launch_bounds__(256)
void prep_feats(const float* __restrict__ feats) {
    const int s = blockIdx.x;
    const int t = threadIdx.x;
    const int n = t >> 1;
    const int kh = (t & 1) * 32;
    const int jb = blockIdx.y * 8;
    uint32_t* out = (uint32_t*)g_fB + (size_t)s * (B_BYTES / 4);
    const float* src = feats + (size_t)(s * BK + kh) * F + n;
#pragma unroll
    for (int j = jb; j < jb + 8; j += 2) {
        const float v0 = src[(size_t)j * F];
        const float v1 = src[(size_t)(j + 1) * F];
        const uint32_t off = (uint32_t)(n * 128 + (kh + j) * 2);
        out[SWX(off) >> 2] = pack_h2(v0, v1);
    }
}

// ---------------------------------------------------------------------------
// Main kernel: split-K x12, BM=128, 16 warps (8m x 2n), 512 threads.
// Same proven stage structure as R9, doubled warp count for latency hiding.
// ---------------------------------------------------------------------------
__global__ __launch_bounds__(THREADS, 1)
void spmm2_f16(const float* __restrict__ node_adj,
               const float* __restrict__ edge_adj) {
    extern __shared__ char smem[];
    const uint32_t sb = smem_u32(smem);
    const int tid  = threadIdx.x;
    const int wid  = tid >> 5;
    const int lane = tid & 31;
    const int M0     = (blockIdx.x % TILES_M) * BM;
    const int kslice = blockIdx.x / TILES_M;
    const size_t K0  = (size_t)kslice * KLEN;

    // ---- converter mapping: thread -> (row cm 0..127, 16-k group kq) ----
    const int cm = tid >> 2;
    const int kq = tid & 3;
    const float* nrow = node_adj + (size_t)(M0 + cm) * N_NODES + K0 + kq * 16;
    const float* erow = edge_adj + (size_t)(M0 + cm) * N_NODES + K0 + kq * 16;
    const uint32_t csts0 = SWX((uint32_t)(cm * 128 + kq * 32));
    const uint32_t csts1 = SWX((uint32_t)(cm * 128 + kq * 32 + 16));

    // ---- mma mapping: 8m x 2n warps, each 16m x 64n per plane ----
    const int wm = (wid & 7) * 16;
    const int wn = (wid >> 3) * 64;
    const uint32_t arow = wm + (lane & 15);
    const uint32_t abase = arow * 128 + (lane >> 4) * 16;
    const uint32_t axor = (arow & 7) << 4;
    uint32_t bbase[4], bxor[4];
#pragma unroll
    for (int np = 0; np < 4; ++np) {
        const uint32_t brow = wn + np * 16 + ((lane >> 4) << 3) + (lane & 7);
        bbase[np] = brow * 128 + ((lane >> 3) & 1) * 16;
        bxor[np]  = (brow & 7) << 4;
    }

    float acc[2][8][4];
#pragma unroll
    for (int p = 0; p < 2; ++p)
#pragma unroll
        for (int nt = 0; nt < 8; ++nt)
#pragma unroll
            for (int c = 0; c < 4; ++c) acc[p][nt][c] = 0.f;

    const char* fB = (const char*)g_fB + (size_t)(kslice * KSTAGES) * B_BYTES;

    // ---- prologue: fill buffer 0 (stage 0) ----
    {
        const uint32_t dst = sb + ST_A2 + tid * 32;
        const char* src = fB + tid * 32;
        CP_ASYNC16(dst, src);
        CP_ASYNC16(dst + 16, src + 16);
    }
    CP_COMMIT();
    {
        float4 n0 = *(const float4*)(nrow);
        float4 n1 = *(const float4*)(nrow + 4);
        float4 n2 = *(const float4*)(nrow + 8);
        float4 n3 = *(const float4*)(nrow + 12);
        float4 e0 = *(const float4*)(erow);
        float4 e1 = *(const float4*)(erow + 4);
        float4 e2 = *(const float4*)(erow + 8);
        float4 e3 = *(const float4*)(erow + 12);
        uint4 S0, S1, E0, E1;
        S0 = make_uint4(pack_h2(sgnf(n0.x), sgnf(n0.y)), pack_h2(sgnf(n0.z), sgnf(n0.w)),
                        pack_h2(sgnf(n1.x), sgnf(n1.y)), pack_h2(sgnf(n1.z), sgnf(n1.w)));
        S1 = make_uint4(pack_h2(sgnf(n2.x), sgnf(n2.y)), pack_h2(sgnf(n2.z), sgnf(n2.w)),
                        pack_h2(sgnf(n3.x), sgnf(n3.y)), pack_h2(sgnf(n3.z), sgnf(n3.w)));
        E0 = make_uint4(pack_h2(e0.x, e0.y), pack_h2(e0.z, e0.w),
                        pack_h2(e1.x, e1.y), pack_h2(e1.z, e1.w));
        E1 = make_uint4(pack_h2(e2.x, e2.y), pack_h2(e2.z, e2.w),
                        pack_h2(e3.x, e3.y), pack_h2(e3.z, e3.w));
        *(uint4*)(smem + 0 * A_BYTES + csts0) = S0;
        *(uint4*)(smem + 0 * A_BYTES + csts1) = S1;
        *(uint4*)(smem + 1 * A_BYTES + csts0) = E0;
        *(uint4*)(smem + 1 * A_BYTES + csts1) = E1;
    }
    CP_WAIT0();
    __syncthreads();

    float4 nv[4], ev[4];

#pragma unroll 1
    for (int s = 0; s < KSTAGES; ++s) {
        const uint32_t cur = (uint32_t)(s & 1) * STAGE_BYTES;
        const uint32_t nxt = (uint32_t)((s + 1) & 1) * STAGE_BYTES;

        // (a) prefetch stage s+1: B via cp.async, adjacency via LDG regs
        if (s + 1 < KSTAGES) {
            {
                const uint32_t dst = sb + nxt + ST_A2 + tid * 32;
                const char* src = fB + (size_t)(s + 1) * B_BYTES + tid * 32;
                CP_ASYNC16(dst, src);
                CP_ASYNC16(dst + 16, src + 16);
            }
            CP_COMMIT();
            const size_t k0 = (size_t)(s + 1) * BK;
#pragma unroll
            for (int i = 0; i < 4; ++i) {
                nv[i] = *(const float4*)(nrow + k0 + i * 4);
                ev[i] = *(const float4*)(erow + k0 + i * 4);
            }
        }

        // (b) compute stage s
        const uint32_t sbA = sb + cur;
        const uint32_t sbB = sb + cur + ST_A2;
#pragma unroll
        for (int ks = 0; ks < 4; ++ks) {
            uint32_t b[4][4];
#pragma unroll
            for (int np = 0; np < 4; ++np)
                LDSM_X4(b[np][0], b[np][1], b[np][2], b[np][3],
                        sbB + ((bbase[np] + ks * 32) ^ bxor[np]));
#pragma unroll
            for (int p = 0; p < 2; ++p) {
                uint32_t a[4];
                LDSM_X4(a[0], a[1], a[2], a[3],
                        sbA + p * A_BYTES + ((abase + ks * 32) ^ axor));
#pragma unroll
                for (int np = 0; np < 4; ++np) {
                    mma_f16(acc[p][np * 2],     a, b[np][0], b[np][1]);
                    mma_f16(acc[p][np * 2 + 1], a, b[np][2], b[np][3]);
                }
            }
        }

        // (c) convert + store stage s+1 A tiles; drain B copy; barrier
        if (s + 1 < KSTAGES) {
            char* bp = smem + ((s + 1) & 1) * STAGE_BYTES;
            uint4 S0, S1, E0, E1;
            S0 = make_uint4(pack_h2(sgnf(nv[0].x), sgnf(nv[0].y)), pack_h2(sgnf(nv[0].z), sgnf(nv[0].w)),
                            pack_h2(sgnf(nv[1].x), sgnf(nv[1].y)), pack_h2(sgnf(nv[1].z), sgnf(nv[1].w)));
            S1 = make_uint4(pack_h2(sgnf(nv[2].x), sgnf(nv[2].y)), pack_h2(sgnf(nv[2].z), sgnf(nv[2].w)),
                            pack_h2(sgnf(nv[3].x), sgnf(nv[3].y)), pack_h2(sgnf(nv[3].z), sgnf(nv[3].w)));
            E0 = make_uint4(pack_h2(ev[0].x, ev[0].y), pack_h2(ev[0].z, ev[0].w),
                            pack_h2(ev[1].x, ev[1].y), pack_h2(ev[1].z, ev[1].w));
            E1 = make_uint4(pack_h2(ev[2].x, ev[2].y), pack_h2(ev[2].z, ev[2].w),
                            pack_h2(ev[3].x, ev[3].y), pack_h2(ev[3].z, ev[3].w));
            *(uint4*)(bp + 0 * A_BYTES + csts0) = S0;
            *(uint4*)(bp + 0 * A_BYTES + csts1) = S1;
            *(uint4*)(bp + 1 * A_BYTES + csts0) = E0;
            *(uint4*)(bp + 1 * A_BYTES + csts1) = E1;
            CP_WAIT0();
            __syncthreads();
        }
    }

    // ---- epilogue: write partial planes for this k-slice ----
    const int er0 = wm + (lane >> 2);
    const int ec0 = wn + (lane & 3) * 2;
#pragma unroll
    for (int p = 0; p < 2; ++p) {
        float* base = g_S + (size_t)kslice * SLICE + (size_t)p * PLANE
                    + (size_t)(M0 + er0) * F + ec0;
#pragma unroll
        for (int nt = 0; nt < 8; ++nt) {
            *(float2*)(base + nt * 8)         = make_float2(acc[p][nt][0], acc[p][nt][1]);
            *(float2*)(base + 8 * F + nt * 8) = make_float2(acc[p][nt][2], acc[p][nt][3]);
        }
    }
}

// ---------------------------------------------------------------------------
// Combine (fused slice-sum, R9 structure):
// out = relu(sum_k Ssign_k @ Wd + b2) + sum_k Sedge_k @ We + eb
// ---------------------------------------------------------------------------
__device__ __forceinline__ void accum_block(const float* __restrict__ W,
                                            const float* __restrict__ S,
                                            float* acc,
                                            float* Ws, float* Ss,
                                            int tid, int tx, int ty, int R0) {
#pragma unroll 1
    for (int k0 = 0; k0 < 128; k0 += 32) {
        __syncthreads();
#pragma unroll
        for (int i = 0; i < 4; ++i) {
            const int e = tid + i * 256;
            const int wrow = e >> 5;
            const int wc = (e & 31) * 4;
            *(float4*)(Ws + wrow * 128 + wc) = *(const float4*)(W + (k0 + wrow) * 128 + wc);
        }
        {
            const int srow = tid >> 3;
            const int sc = (tid & 7) * 4;
            const size_t gi = (size_t)(R0 + srow) * F + k0 + sc;
            float4 t = *(const float4*)(S + gi);
#pragma unroll
            for (int sl = 1; sl < KSPLIT; ++sl) {
                float4 a = *(const float4*)(S + (size_t)sl * SLICE + gi);
                t.x += a.x; t.y += a.y; t.z += a.z; t.w += a.w;
            }
            *(float4*)(Ss + srow * 36 + sc) = t;
        }
        __syncthreads();
#pragma unroll 8
        for (int kk = 0; kk < 32; ++kk) {
            float w[4], sv[4];
#pragma unroll
            for (int v = 0; v < 4; ++v) w[v] = Ws[kk * 128 + tx + 32 * v];
#pragma unroll
            for (int u = 0; u < 4; ++u) sv[u] = Ss[(ty + 8 * u) * 36 + kk];
#pragma unroll
            for (int u = 0; u < 4; ++u)
#pragma unroll
                for (int v = 0; v < 4; ++v)
                    acc[u * 4 + v] = fmaf(sv[u], w[v], acc[u * 4 + v]);
        }
    }
}

__global__ __launch_bounds__(256)
void combine_kernel(const float* __restrict__ edge_weight,
                    const float* __restrict__ edge_bias,
                    float* __restrict__ out) {
    __shared__ float Ws[32 * 128];
    __shared__ float Ss[32 * 36];

    const int tid = threadIdx.x;
    const int tx = tid & 31;
    const int ty = tid >> 5;
    const int R0 = blockIdx.x * 32;

    float accN[16], accE[16];
#pragma unroll
    for (int i = 0; i < 16; ++i) { accN[i] = 0.f; accE[i] = 0.f; }

    accum_block(g_Wd,        g_S,         accN, Ws, Ss, tid, tx, ty, R0);
    accum_block(edge_weight, g_S + PLANE, accE, Ws, Ss, tid, tx, ty, R0);

    float b2[4], eb[4];
#pragma unroll
    for (int v = 0; v < 4; ++v) {
        b2[v] = g_b2[tx + 32 * v];
        eb[v] = edge_bias[tx + 32 * v];
    }
#pragma unroll
    for (int u = 0; u < 4; ++u)
#pragma unroll
        for (int v = 0; v < 4; ++v) {
            const int rr = R0 + ty + 8 * u;
            const int c = tx + 32 * v;
            out[(size_t)rr * F + c] =
                fmaxf(accN[u * 4 + v] + b2[v], 0.f) + accE[u * 4 + v] + eb[v];
        }
}

extern "C" void kernel_launch(void* const* d_in, const int* in_sizes, int n_in,
                              void* d_out, int out_size) {
    const float* feats       = (const float*)d_in[0];
    const float* node_adj    = (const float*)d_in[1];
    const float* edge_adj    = (const float*)d_in[2];
    const float* node_weight = (const float*)d_in[3];
    const float* node_bias   = (const float*)d_in[4];
    const float* edge_weight = (const float*)d_in[5];
    const float* edge_bias   = (const float*)d_in[6];
    float* out = (float*)d_out;

    cudaFuncSetAttribute(spmm2_f16, cudaFuncAttributeMaxDynamicSharedMemorySize, SMEM_TOTAL);

    colsum_kernel<<<96, 128>>>(feats);
    wtrans_kernel<<<1, 128>>>(node_weight, node_bias);
    prep_feats<<<dim3(N_NODES / BK, 4), 256>>>(feats);
    spmm2_f16<<<GRID, THREADS, SMEM_TOTAL>>>(node_adj, edge_adj);
    combine_kernel<<<N_NODES / 32, 256>>>(edge_weight, edge_bias, out);
}

// round 13
// speedup vs baseline: 1.6899x; 1.6899x over previous
#include <cuda_runtime.h>
#include <cuda_fp16.h>
#include <cstdint>
#include <cstddef>

#define N_NODES 12288
#define F 128
#define BM 128
#define BK 64
#define KSPLIT 12
#define KLEN (N_NODES / KSPLIT)     // 1024
#define KSTAGES (KLEN / BK)         // 16
#define TILES_M (N_NODES / BM)      // 96
#define GRID (TILES_M * KSPLIT)     // 1152
#define THREADS 512

#define A_BYTES (BM * 128)          // 16384 per A plane
#define ST_A2   (2 * A_BYTES)       // 32768: [sign][edge]
#define B_BYTES (128 * 128)         // 16384
#define STAGE_BYTES (ST_A2 + B_BYTES)   // 49152
#define SM_MAIN (2 * STAGE_BYTES)       // 98304
#define STG_NODE SM_MAIN                // raw fp32 adjacency staging (32KB)
#define STG_EDGE (SM_MAIN + 32768)      // 32KB
#define SMEM_TOTAL (SM_MAIN + 65536)    // 163840

#define PLANE ((size_t)N_NODES * F)
#define SLICE (2 * PLANE)

// Scratch
__device__ float g_S[(size_t)KSPLIT * 2 * N_NODES * F];   // ~151 MB partials
__device__ uint4 g_fB[(size_t)(N_NODES / BK) * B_BYTES / 16];
__device__ float g_cpart[96 * F];
__device__ float g_Wd[F * F];
__device__ float g_b2[F];

// ---------------------------------------------------------------------------
// helpers
// ---------------------------------------------------------------------------
__device__ __forceinline__ uint32_t smem_u32(const void* p) {
    uint32_t a;
    asm("{ .reg .u64 t; cvta.to.shared.u64 t, %1; cvt.u32.u64 %0, t; }"
        : "=r"(a) : "l"(p));
    return a;
}

__device__ __forceinline__ uint32_t pack_h2(float lo, float hi) {
    __half2 h = __floats2half2_rn(lo, hi);
    return *(uint32_t*)&h;
}

__device__ __forceinline__ float sgnf(float v) {
    return (v > 0.f ? 1.f : 0.f) - (v < 0.f ? 1.f : 0.f);
}

#define SWX(off) ((off) ^ (((off) >> 3) & 0x70))
// staging: per-thread 64B block, XOR keeps 8-lane phases conflict-free
#define SSTG(t, q) ((uint32_t)(((t) * 64 + (q) * 16) ^ (((t) & 6) << 3)))

#define CP_ASYNC16(dst_u32, src) \
    asm volatile("cp.async.cg.shared.global [%0], [%1], 16;" \
                 :: "r"(dst_u32), "l"(src) : "memory")
#define CP_COMMIT() asm volatile("cp.async.commit_group;" ::: "memory")
#define CP_WAIT0()  asm volatile("cp.async.wait_group 0;" ::: "memory")

#define LDS128F(v, addr) \
    asm volatile("ld.shared.v4.f32 {%0,%1,%2,%3}, [%4];" \
                 : "=f"((v).x), "=f"((v).y), "=f"((v).z), "=f"((v).w) : "r"(addr))

#define LDSM_X4(r0, r1, r2, r3, addr) \
    asm volatile("ldmatrix.sync.aligned.m8n8.x4.shared.b16 {%0,%1,%2,%3}, [%4];" \
                 : "=r"(r0), "=r"(r1), "=r"(r2), "=r"(r3) : "r"(addr))

__device__ __forceinline__ void mma_f16(float* d, const uint32_t* a,
                                        uint32_t b0, uint32_t b1) {
    asm volatile(
        "mma.sync.aligned.m16n8k16.row.col.f32.f16.f16.f32 "
        "{%0,%1,%2,%3}, {%4,%5,%6,%7}, {%8,%9}, {%0,%1,%2,%3};\n"
        : "+f"(d[0]), "+f"(d[1]), "+f"(d[2]), "+f"(d[3])
        : "r"(a[0]), "r"(a[1]), "r"(a[2]), "r"(a[3]), "r"(b0), "r"(b1));
}

// ---------------------------------------------------------------------------
// Prepass kernels
// ---------------------------------------------------------------------------
__global__ __launch_bounds__(128)
void colsum_kernel(const float* __restrict__ feats) {
    const int t = threadIdx.x;
    const int r0 = blockIdx.x * 128;
    float s = 0.f;
#pragma unroll 4
    for (int r = 0; r < 128; ++r)
        s += feats[(size_t)(r0 + r) * F + t];
    g_cpart[blockIdx.x * F + t] = s;
}

__global__ __launch_bounds__(128)
void wtrans_kernel(const float* __restrict__ node_weight,
                   const float* __restrict__ node_bias) {
    __shared__ float cs[F];
    const int j = threadIdx.x;
    {
        float c = 0.f;
#pragma unroll 4
        for (int b = 0; b < 96; ++b)
            c += g_cpart[b * F + j];
        cs[j] = c;
    }
    __syncthreads();
    float b = node_bias[j];
#pragma unroll 4
    for (int k = 0; k < 128; ++k) {
        const float wt = node_weight[(size_t)k * F + j];
        const float wb = node_weight[(size_t)(k + 128) * F + j];
        g_Wd[k * F + j] = 0.5f * (wt - wb);
        b += cs[k] * 0.5f * (wt + wb);
    }
    g_b2[j] = b;
}

__global__ __launch_bounds__(256)
void prep_feats(const float* __restrict__ feats) {
    const int s = blockIdx.x;
    const int t = threadIdx.x;
    const int n = t >> 1;
    const int kh = (t & 1) * 32;
    const int jb = blockIdx.y * 8;
    uint32_t* out = (uint32_t*)g_fB + (size_t)s * (B_BYTES / 4);
    const float* src = feats + (size_t)(s * BK + kh) * F + n;
#pragma unroll
    for (int j = jb; j < jb + 8; j += 2) {
        const float v0 = src[(size_t)j * F];
        const float v1 = src[(size_t)(j + 1) * F];
        const uint32_t off = (uint32_t)(n * 128 + (kh + j) * 2);
        out[SWX(off) >> 2] = pack_h2(v0, v1);
    }
}

// ---------------------------------------------------------------------------
// Main kernel: split-K x12, BM=128, 16 warps (8m x 2n), 512 threads.
// Adjacency staged via cp.async (no prefetch registers -> fits 128-reg cap).
// ---------------------------------------------------------------------------
__global__ __launch_bounds__(THREADS, 1)
void spmm2_f16(const float* __restrict__ node_adj,
               const float* __restrict__ edge_adj) {
    extern __shared__ char smem[];
    const uint32_t sb = smem_u32(smem);
    const int tid  = threadIdx.x;
    const int wid  = tid >> 5;
    const int lane = tid & 31;
    const int M0     = (blockIdx.x % TILES_M) * BM;
    const int kslice = blockIdx.x / TILES_M;
    const size_t K0  = (size_t)kslice * KLEN;

    // ---- converter mapping: thread -> (row cm 0..127, 16-k group kq) ----
    const int cm = tid >> 2;
    const int kq = tid & 3;
    const float* nrow = node_adj + (size_t)(M0 + cm) * N_NODES + K0 + kq * 16;
    const float* erow = edge_adj + (size_t)(M0 + cm) * N_NODES + K0 + kq * 16;
    const uint32_t csts0 = SWX((uint32_t)(cm * 128 + kq * 32));
    const uint32_t csts1 = SWX((uint32_t)(cm * 128 + kq * 32 + 16));
    const uint32_t stgN = sb + STG_NODE + SSTG(tid, 0);
    const uint32_t stgE = sb + STG_EDGE + SSTG(tid, 0);
    // SSTG(t,q) = SSTG(t,0) + q*16 (XOR bits don't overlap q*16 bits 4-5? they do:
    // xor term is ((t&6)<<3) in {0,16,32,48}; add q*16 before xor => precompute all 4)
    uint32_t stgNq[4], stgEq[4];
#pragma unroll
    for (int q = 0; q < 4; ++q) {
        stgNq[q] = sb + STG_NODE + SSTG(tid, q);
        stgEq[q] = sb + STG_EDGE + SSTG(tid, q);
    }
    (void)stgN; (void)stgE;

    // ---- mma mapping: 8m x 2n warps ----
    const int wm = (wid & 7) * 16;
    const int wn = (wid >> 3) * 64;
    const uint32_t arow = wm + (lane & 15);
    const uint32_t abase = arow * 128 + (lane >> 4) * 16;
    const uint32_t axor = (arow & 7) << 4;
    uint32_t bbase[4], bxor[4];
#pragma unroll
    for (int np = 0; np < 4; ++np) {
        const uint32_t brow = wn + np * 16 + ((lane >> 4) << 3) + (lane & 7);
        bbase[np] = brow * 128 + ((lane >> 3) & 1) * 16;
        bxor[np]  = (brow & 7) << 4;
    }

    float acc[2][8][4];
#pragma unroll
    for (int p = 0; p < 2; ++p)
#pragma unroll
        for (int nt = 0; nt < 8; ++nt)
#pragma unroll
            for (int c = 0; c < 4; ++c) acc[p][nt][c] = 0.f;

    const char* fB = (const char*)g_fB + (size_t)(kslice * KSTAGES) * B_BYTES;

    // staging fill for stage s (raw adjacency, 64B per thread per matrix)
    auto stage_adj = [&](int s) {
        const size_t k0 = (size_t)s * BK;
#pragma unroll
        for (int q = 0; q < 4; ++q) {
            CP_ASYNC16(stgNq[q], nrow + k0 + q * 4);
            CP_ASYNC16(stgEq[q], erow + k0 + q * 4);
        }
    };
    // B tile fill for stage s into buffer off
    auto stage_B = [&](int s, uint32_t buf_off) {
        const uint32_t dst = sb + buf_off + ST_A2 + tid * 32;
        const char* src = fB + (size_t)s * B_BYTES + tid * 32;
        CP_ASYNC16(dst, src);
        CP_ASYNC16(dst + 16, src + 16);
    };
    // convert staging -> A tiles of buffer dbuf
    auto convert = [&](uint32_t dbuf_off) {
        float4 n0, n1, n2, n3, e0, e1, e2, e3;
        LDS128F(n0, stgNq[0]); LDS128F(n1, stgNq[1]);
        LDS128F(n2, stgNq[2]); LDS128F(n3, stgNq[3]);
        LDS128F(e0, stgEq[0]); LDS128F(e1, stgEq[1]);
        LDS128F(e2, stgEq[2]); LDS128F(e3, stgEq[3]);
        char* bp = smem + dbuf_off;
        uint4 S0, S1, E0, E1;
        S0 = make_uint4(pack_h2(sgnf(n0.x), sgnf(n0.y)), pack_h2(sgnf(n0.z), sgnf(n0.w)),
                        pack_h2(sgnf(n1.x), sgnf(n1.y)), pack_h2(sgnf(n1.z), sgnf(n1.w)));
        S1 = make_uint4(pack_h2(sgnf(n2.x), sgnf(n2.y)), pack_h2(sgnf(n2.z), sgnf(n2.w)),
                        pack_h2(sgnf(n3.x), sgnf(n3.y)), pack_h2(sgnf(n3.z), sgnf(n3.w)));
        E0 = make_uint4(pack_h2(e0.x, e0.y), pack_h2(e0.z, e0.w),
                        pack_h2(e1.x, e1.y), pack_h2(e1.z, e1.w));
        E1 = make_uint4(pack_h2(e2.x, e2.y), pack_h2(e2.z, e2.w),
                        pack_h2(e3.x, e3.y), pack_h2(e3.z, e3.w));
        *(uint4*)(bp + 0 * A_BYTES + csts0) = S0;
        *(uint4*)(bp + 0 * A_BYTES + csts1) = S1;
        *(uint4*)(bp + 1 * A_BYTES + csts0) = E0;
        *(uint4*)(bp + 1 * A_BYTES + csts1) = E1;
    };

    // ---- prologue ----
    stage_B(0, 0);
    stage_adj(0);
    CP_COMMIT();
    CP_WAIT0();
    convert(0);
    stage_adj(1);
    CP_COMMIT();
    __syncthreads();

#pragma unroll 1
    for (int s = 0; s < KSTAGES; ++s) {
        const uint32_t cur = (uint32_t)(s & 1) * STAGE_BYTES;
        const uint32_t nxt = (uint32_t)((s + 1) & 1) * STAGE_BYTES;

        // (a) B copy for stage s+1
        if (s + 1 < KSTAGES) {
            stage_B(s + 1, nxt);
            CP_COMMIT();
        }

        // (b) compute stage s
        const uint32_t sbA = sb + cur;
        const uint32_t sbB = sb + cur + ST_A2;
#pragma unroll
        for (int ks = 0; ks < 4; ++ks) {
            uint32_t b[4][4];
#pragma unroll
            for (int np = 0; np < 4; ++np)
                LDSM_X4(b[np][0], b[np][1], b[np][2], b[np][3],
                        sbB + ((bbase[np] + ks * 32) ^ bxor[np]));
#pragma unroll
            for (int p = 0; p < 2; ++p) {
                uint32_t a[4];
                LDSM_X4(a[0], a[1], a[2], a[3],
                        sbA + p * A_BYTES + ((abase + ks * 32) ^ axor));
#pragma unroll
                for (int np = 0; np < 4; ++np) {
                    mma_f16(acc[p][np * 2],     a, b[np][0], b[np][1]);
                    mma_f16(acc[p][np * 2 + 1], a, b[np][2], b[np][3]);
                }
            }
        }

        // (c) drain copies; convert staging (s+1) into nxt; refill staging (s+2)
        if (s + 1 < KSTAGES) {
            CP_WAIT0();
            convert(nxt);
            if (s + 2 < KSTAGES) {
                stage_adj(s + 2);
                CP_COMMIT();
            }
            __syncthreads();
        }
    }

    // ---- epilogue: write partial planes for this k-slice ----
    const int er0 = wm + (lane >> 2);
    const int ec0 = wn + (lane & 3) * 2;
#pragma unroll
    for (int p = 0; p < 2; ++p) {
        float* base = g_S + (size_t)kslice * SLICE + (size_t)p * PLANE
                    + (size_t)(M0 + er0) * F + ec0;
#pragma unroll
        for (int nt = 0; nt < 8; ++nt) {
            *(float2*)(base + nt * 8)         = make_float2(acc[p][nt][0], acc[p][nt][1]);
            *(float2*)(base + 8 * F + nt * 8) = make_float2(acc[p][nt][2], acc[p][nt][3]);
        }
    }
}

// ---------------------------------------------------------------------------
// Combine (fused slice-sum): out = relu(sum Ssign@Wd + b2) + sum Sedge@We + eb
// ---------------------------------------------------------------------------
__device__ __forceinline__ void accum_block(const float* __restrict__ W,
                                            const float* __restrict__ S,
                                            float* acc,
                                            float* Ws, float* Ss,
                                            int tid, int tx, int ty, int R0) {
#pragma unroll 1
    for (int k0 = 0; k0 < 128; k0 += 32) {
        __syncthreads();
#pragma unroll
        for (int i = 0; i < 4; ++i) {
            const int e = tid + i * 256;
            const int wrow = e >> 5;
            const int wc = (e & 31) * 4;
            *(float4*)(Ws + wrow * 128 + wc) = *(const float4*)(W + (k0 + wrow) * 128 + wc);
        }
        {
            const int srow = tid >> 3;
            const int sc = (tid & 7) * 4;
            const size_t gi = (size_t)(R0 + srow) * F + k0 + sc;
            float4 t = *(const float4*)(S + gi);
#pragma unroll
            for (int sl = 1; sl < KSPLIT; ++sl) {
                float4 a = *(const float4*)(S + (size_t)sl * SLICE + gi);
                t.x += a.x; t.y += a.y; t.z += a.z; t.w += a.w;
            }
            *(float4*)(Ss + srow * 36 + sc) = t;
        }
        __syncthreads();
#pragma unroll 8
        for (int kk = 0; kk < 32; ++kk) {
            float w[4], sv[4];
#pragma unroll
            for (int v = 0; v < 4; ++v) w[v] = Ws[kk * 128 + tx + 32 * v];
#pragma unroll
            for (int u = 0; u < 4; ++u) sv[u] = Ss[(ty + 8 * u) * 36 + kk];
#pragma unroll
            for (int u = 0; u < 4; ++u)
#pragma unroll
                for (int v = 0; v < 4; ++v)
                    acc[u * 4 + v] = fmaf(sv[u], w[v], acc[u * 4 + v]);
        }
    }
}

__global__ __launch_bounds__(256)
void combine_kernel(const float* __restrict__ edge_weight,
                    const float* __restrict__ edge_bias,
                    float* __restrict__ out) {
    __shared__ float Ws[32 * 128];
    __shared__ float Ss[32 * 36];

    const int tid = threadIdx.x;
    const int tx = tid & 31;
    const int ty = tid >> 5;
    const int R0 = blockIdx.x * 32;

    float accN[16], accE[16];
#pragma unroll
    for (int i = 0; i < 16; ++i) { accN[i] = 0.f; accE[i] = 0.f; }

    accum_block(g_Wd,        g_S,         accN, Ws, Ss, tid, tx, ty, R0);
    accum_block(edge_weight, g_S + PLANE, accE, Ws, Ss, tid, tx, ty, R0);

    float b2[4], eb[4];
#pragma unroll
    for (int v = 0; v < 4; ++v) {
        b2[v] = g_b2[tx + 32 * v];
        eb[v] = edge_bias[tx + 32 * v];
    }
#pragma unroll
    for (int u = 0; u < 4; ++u)
#pragma unroll
        for (int v = 0; v < 4; ++v) {
            const int rr = R0 + ty + 8 * u;
            const int c = tx + 32 * v;
            out[(size_t)rr * F + c] =
                fmaxf(accN[u * 4 + v] + b2[v], 0.f) + accE[u * 4 + v] + eb[v];
        }
}

extern "C" void kernel_launch(void* const* d_in, const int* in_sizes, int n_in,
                              void* d_out, int out_size) {
    const float* feats       = (const float*)d_in[0];
    const float* node_adj    = (const float*)d_in[1];
    const float* edge_adj    = (const float*)d_in[2];
    const float* node_weight = (const float*)d_in[3];
    const float* node_bias   = (const float*)d_in[4];
    const float* edge_weight = (const float*)d_in[5];
    const float* edge_bias   = (const float*)d_in[6];
    float* out = (float*)d_out;

    cudaFuncSetAttribute(spmm2_f16, cudaFuncAttributeMaxDynamicSharedMemorySize, SMEM_TOTAL);

    colsum_kernel<<<96, 128>>>(feats);
    wtrans_kernel<<<1, 128>>>(node_weight, node_bias);
    prep_feats<<<dim3(N_NODES / BK, 4), 256>>>(feats);
    spmm2_f16<<<GRID, THREADS, SMEM_TOTAL>>>(node_adj, edge_adj);
    combine_kernel<<<N_NODES / 32, 256>>>(edge_weight, edge_bias, out);
}

// round 14
// speedup vs baseline: 1.7028x; 1.0076x over previous
#include <cuda_runtime.h>
#include <cuda_fp16.h>
#include <cstdint>
#include <cstddef>

#define N_NODES 12288
#define F 128
#define BM 128
#define BK 64
#define KSPLIT 12
#define KLEN (N_NODES / KSPLIT)     // 1024
#define KSTAGES (KLEN / BK)         // 16
#define TILES_M (N_NODES / BM)      // 96
#define GRID (TILES_M * KSPLIT)     // 1152
#define THREADS 512

#define A_BYTES (BM * 128)          // 16384 per A plane
#define ST_A2   (2 * A_BYTES)       // 32768: [sign][edge]
#define B_BYTES (128 * 128)         // 16384
#define STAGE_BYTES (ST_A2 + B_BYTES)   // 49152
#define SM_MAIN (2 * STAGE_BYTES)       // 98304
#define STG_NODE SM_MAIN                // raw fp32 adjacency staging (32KB)
#define STG_EDGE (SM_MAIN + 32768)      // 32KB
#define SMEM_TOTAL (SM_MAIN + 65536)    // 163840

#define FH (F / 2)                      // 64 uints per row (fp16 pairs)
#define PLANE_H ((size_t)N_NODES * FH)  // one fp16 plane in uints
#define SLICE_H (2 * PLANE_H)

// Scratch: fp16 partial planes (75.5 MB), fp16 featsT tiles, folded W
__device__ uint32_t g_S[(size_t)KSPLIT * 2 * N_NODES * FH];
__device__ uint4 g_fB[(size_t)(N_NODES / BK) * B_BYTES / 16];
__device__ float g_cpart[96 * F];
__device__ float g_Wd[F * F];
__device__ float g_b2[F];

// ---------------------------------------------------------------------------
// helpers
// ---------------------------------------------------------------------------
__device__ __forceinline__ uint32_t smem_u32(const void* p) {
    uint32_t a;
    asm("{ .reg .u64 t; cvta.to.shared.u64 t, %1; cvt.u32.u64 %0, t; }"
        : "=r"(a) : "l"(p));
    return a;
}

__device__ __forceinline__ uint32_t pack_h2(float lo, float hi) {
    __half2 h = __floats2half2_rn(lo, hi);
    return *(uint32_t*)&h;
}

__device__ __forceinline__ float sgnf(float v) {
    return (v > 0.f ? 1.f : 0.f) - (v < 0.f ? 1.f : 0.f);
}

#define SWX(off) ((off) ^ (((off) >> 3) & 0x70))
#define SSTG(t, q) ((uint32_t)(((t) * 64 + (q) * 16) ^ (((t) & 6) << 3)))

#define CP_ASYNC16(dst_u32, src) \
    asm volatile("cp.async.cg.shared.global [%0], [%1], 16;" \
                 :: "r"(dst_u32), "l"(src) : "memory")
#define CP_COMMIT() asm volatile("cp.async.commit_group;" ::: "memory")
#define CP_WAIT0()  asm volatile("cp.async.wait_group 0;" ::: "memory")

#define LDS128F(v, addr) \
    asm volatile("ld.shared.v4.f32 {%0,%1,%2,%3}, [%4];" \
                 : "=f"((v).x), "=f"((v).y), "=f"((v).z), "=f"((v).w) : "r"(addr))

#define LDSM_X4(r0, r1, r2, r3, addr) \
    asm volatile("ldmatrix.sync.aligned.m8n8.x4.shared.b16 {%0,%1,%2,%3}, [%4];" \
                 : "=r"(r0), "=r"(r1), "=r"(r2), "=r"(r3) : "r"(addr))

__device__ __forceinline__ void mma_f16(float* d, const uint32_t* a,
                                        uint32_t b0, uint32_t b1) {
    asm volatile(
        "mma.sync.aligned.m16n8k16.row.col.f32.f16.f16.f32 "
        "{%0,%1,%2,%3}, {%4,%5,%6,%7}, {%8,%9}, {%0,%1,%2,%3};\n"
        : "+f"(d[0]), "+f"(d[1]), "+f"(d[2]), "+f"(d[3])
        : "r"(a[0]), "r"(a[1]), "r"(a[2]), "r"(a[3]), "r"(b0), "r"(b1));
}

// ---------------------------------------------------------------------------
// Prepass kernels
// ---------------------------------------------------------------------------
__global__ __launch_bounds__(128)
void colsum_kernel(const float* __restrict__ feats) {
    const int t = threadIdx.x;
    const int r0 = blockIdx.x * 128;
    float s = 0.f;
#pragma unroll 4
    for (int r = 0; r < 128; ++r)
        s += feats[(size_t)(r0 + r) * F + t];
    g_cpart[blockIdx.x * F + t] = s;
}

__global__ __launch_bounds__(128)
void wtrans_kernel(const float* __restrict__ node_weight,
                   const float* __restrict__ node_bias) {
    __shared__ float cs[F];
    const int j = threadIdx.x;
    {
        float c = 0.f;
#pragma unroll 4
        for (int b = 0; b < 96; ++b)
            c += g_cpart[b * F + j];
        cs[j] = c;
    }
    __syncthreads();
    float b = node_bias[j];
#pragma unroll 4
    for (int k = 0; k < 128; ++k) {
        const float wt = node_weight[(size_t)k * F + j];
        const float wb = node_weight[(size_t)(k + 128) * F + j];
        g_Wd[k * F + j] = 0.5f * (wt - wb);
        b += cs[k] * 0.5f * (wt + wb);
    }
    g_b2[j] = b;
}

__global__ __launch_bounds__(256)
void prep_feats(const float* __restrict__ feats) {
    const int s = blockIdx.x;
    const int t = threadIdx.x;
    const int n = t >> 1;
    const int kh = (t & 1) * 32;
    const int jb = blockIdx.y * 8;
    uint32_t* out = (uint32_t*)g_fB + (size_t)s * (B_BYTES / 4);
    const float* src = feats + (size_t)(s * BK + kh) * F + n;
#pragma unroll
    for (int j = jb; j < jb + 8; j += 2) {
        const float v0 = src[(size_t)j * F];
        const float v1 = src[(size_t)(j + 1) * F];
        const uint32_t off = (uint32_t)(n * 128 + (kh + j) * 2);
        out[SWX(off) >> 2] = pack_h2(v0, v1);
    }
}

// ---------------------------------------------------------------------------
// Main kernel: split-K x12, BM=128, 16 warps (8m x 2n), 512 threads.
// Adjacency staged via cp.async; convert split node/edge to cap live regs.
// ---------------------------------------------------------------------------
__global__ __launch_bounds__(THREADS, 1)
void spmm2_f16(const float* __restrict__ node_adj,
               const float* __restrict__ edge_adj) {
    extern __shared__ char smem[];
    const uint32_t sb = smem_u32(smem);
    const int tid  = threadIdx.x;
    const int wid  = tid >> 5;
    const int lane = tid & 31;
    const int M0     = (blockIdx.x % TILES_M) * BM;
    const int kslice = blockIdx.x / TILES_M;
    const size_t K0  = (size_t)kslice * KLEN;

    // ---- converter mapping ----
    const int cm = tid >> 2;
    const int kq = tid & 3;
    const float* nrow = node_adj + (size_t)(M0 + cm) * N_NODES + K0 + kq * 16;
    const float* erow = edge_adj + (size_t)(M0 + cm) * N_NODES + K0 + kq * 16;
    const uint32_t csts0 = SWX((uint32_t)(cm * 128 + kq * 32));
    const uint32_t csts1 = SWX((uint32_t)(cm * 128 + kq * 32 + 16));
    uint32_t stgNq[4], stgEq[4];
#pragma unroll
    for (int q = 0; q < 4; ++q) {
        stgNq[q] = sb + STG_NODE + SSTG(tid, q);
        stgEq[q] = sb + STG_EDGE + SSTG(tid, q);
    }

    // ---- mma mapping: 8m x 2n warps ----
    const int wm = (wid & 7) * 16;
    const int wn = (wid >> 3) * 64;
    const uint32_t arow = wm + (lane & 15);
    const uint32_t abase = arow * 128 + (lane >> 4) * 16;
    const uint32_t axor = (arow & 7) << 4;
    uint32_t bbase[4], bxor[4];
#pragma unroll
    for (int np = 0; np < 4; ++np) {
        const uint32_t brow = wn + np * 16 + ((lane >> 4) << 3) + (lane & 7);
        bbase[np] = brow * 128 + ((lane >> 3) & 1) * 16;
        bxor[np]  = (brow & 7) << 4;
    }

    float acc[2][8][4];
#pragma unroll
    for (int p = 0; p < 2; ++p)
#pragma unroll
        for (int nt = 0; nt < 8; ++nt)
#pragma unroll
            for (int c = 0; c < 4; ++c) acc[p][nt][c] = 0.f;

    const char* fB = (const char*)g_fB + (size_t)(kslice * KSTAGES) * B_BYTES;

    auto stage_adj = [&](int s) {
        const size_t k0 = (size_t)s * BK;
#pragma unroll
        for (int q = 0; q < 4; ++q) {
            CP_ASYNC16(stgNq[q], nrow + k0 + q * 4);
            CP_ASYNC16(stgEq[q], erow + k0 + q * 4);
        }
    };
    auto stage_B = [&](int s, uint32_t buf_off) {
        const uint32_t dst = sb + buf_off + ST_A2 + tid * 32;
        const char* src = fB + (size_t)s * B_BYTES + tid * 32;
        CP_ASYNC16(dst, src);
        CP_ASYNC16(dst + 16, src + 16);
    };
    // convert in two halves to cap live registers (spill avoidance)
    auto convert = [&](uint32_t dbuf_off) {
        char* bp = smem + dbuf_off;
        {
            float4 n0, n1, n2, n3;
            LDS128F(n0, stgNq[0]); LDS128F(n1, stgNq[1]);
            LDS128F(n2, stgNq[2]); LDS128F(n3, stgNq[3]);
            uint4 S0, S1;
            S0 = make_uint4(pack_h2(sgnf(n0.x), sgnf(n0.y)), pack_h2(sgnf(n0.z), sgnf(n0.w)),
                            pack_h2(sgnf(n1.x), sgnf(n1.y)), pack_h2(sgnf(n1.z), sgnf(n1.w)));
            S1 = make_uint4(pack_h2(sgnf(n2.x), sgnf(n2.y)), pack_h2(sgnf(n2.z), sgnf(n2.w)),
                            pack_h2(sgnf(n3.x), sgnf(n3.y)), pack_h2(sgnf(n3.z), sgnf(n3.w)));
            *(uint4*)(bp + 0 * A_BYTES + csts0) = S0;
            *(uint4*)(bp + 0 * A_BYTES + csts1) = S1;
        }
        {
            float4 e0, e1, e2, e3;
            LDS128F(e0, stgEq[0]); LDS128F(e1, stgEq[1]);
            LDS128F(e2, stgEq[2]); LDS128F(e3, stgEq[3]);
            uint4 E0, E1;
            E0 = make_uint4(pack_h2(e0.x, e0.y), pack_h2(e0.z, e0.w),
                            pack_h2(e1.x, e1.y), pack_h2(e1.z, e1.w));
            E1 = make_uint4(pack_h2(e2.x, e2.y), pack_h2(e2.z, e2.w),
                            pack_h2(e3.x, e3.y), pack_h2(e3.z, e3.w));
            *(uint4*)(bp + 1 * A_BYTES + csts0) = E0;
            *(uint4*)(bp + 1 * A_BYTES + csts1) = E1;
        }
    };

    // ---- prologue ----
    stage_B(0, 0);
    stage_adj(0);
    CP_COMMIT();
    CP_WAIT0();
    convert(0);
    stage_adj(1);
    CP_COMMIT();
    __syncthreads();

#pragma unroll 1
    for (int s = 0; s < KSTAGES; ++s) {
        const uint32_t cur = (uint32_t)(s & 1) * STAGE_BYTES;
        const uint32_t nxt = (uint32_t)((s + 1) & 1) * STAGE_BYTES;

        if (s + 1 < KSTAGES) {
            stage_B(s + 1, nxt);
            CP_COMMIT();
        }

        const uint32_t sbA = sb + cur;
        const uint32_t sbB = sb + cur + ST_A2;
#pragma unroll
        for (int ks = 0; ks < 4; ++ks) {
            uint32_t b[4][4];
#pragma unroll
            for (int np = 0; np < 4; ++np)
                LDSM_X4(b[np][0], b[np][1], b[np][2], b[np][3],
                        sbB + ((bbase[np] + ks * 32) ^ bxor[np]));
#pragma unroll
            for (int p = 0; p < 2; ++p) {
                uint32_t a[4];
                LDSM_X4(a[0], a[1], a[2], a[3],
                        sbA + p * A_BYTES + ((abase + ks * 32) ^ axor));
#pragma unroll
                for (int np = 0; np < 4; ++np) {
                    mma_f16(acc[p][np * 2],     a, b[np][0], b[np][1]);
                    mma_f16(acc[p][np * 2 + 1], a, b[np][2], b[np][3]);
                }
            }
        }

        if (s + 1 < KSTAGES) {
            CP_WAIT0();
            convert(nxt);
            if (s + 2 < KSTAGES) {
                stage_adj(s + 2);
                CP_COMMIT();
            }
            __syncthreads();
        }
    }

    // ---- epilogue: write fp16 partial planes for this k-slice ----
    const int er0 = wm + (lane >> 2);
    const int ec0 = wn + (lane & 3) * 2;      // even column
#pragma unroll
    for (int p = 0; p < 2; ++p) {
        uint32_t* base = g_S + (size_t)kslice * SLICE_H + (size_t)p * PLANE_H
                       + (size_t)(M0 + er0) * FH + (ec0 >> 1);
#pragma unroll
        for (int nt = 0; nt < 8; ++nt) {
            base[nt * 4]          = pack_h2(acc[p][nt][0], acc[p][nt][1]);
            base[8 * FH + nt * 4] = pack_h2(acc[p][nt][2], acc[p][nt][3]);
        }
    }
}

// ---------------------------------------------------------------------------
// Combine (fp16 partials, fused slice-sum in fp32):
// out = relu(sum Ssign@Wd + b2) + sum Sedge@We + eb
// ---------------------------------------------------------------------------
__device__ __forceinline__ void accum_block(const float* __restrict__ W,
                                            const uint32_t* __restrict__ S,
                                            float* acc,
                                            float* Ws, float* Ss,
                                            int tid, int tx, int ty, int R0) {
#pragma unroll 1
    for (int k0 = 0; k0 < 128; k0 += 32) {
        __syncthreads();
#pragma unroll
        for (int i = 0; i < 4; ++i) {
            const int e = tid + i * 256;
            const int wrow = e >> 5;
            const int wc = (e & 31) * 4;
            *(float4*)(Ws + wrow * 128 + wc) = *(const float4*)(W + (k0 + wrow) * 128 + wc);
        }
        {
            const int srow = tid >> 3;
            const int sc = (tid & 7) * 4;     // float column (even, step 4)
            const uint32_t* Sh = S + (size_t)(R0 + srow) * FH + ((k0 + sc) >> 1);
            float2 t0 = make_float2(0.f, 0.f), t1 = make_float2(0.f, 0.f);
#pragma unroll
            for (int sl = 0; sl < KSPLIT; ++sl) {
                const uint2 v = *(const uint2*)(Sh + (size_t)sl * SLICE_H);
                const float2 a0 = __half22float2(*(const __half2*)&v.x);
                const float2 a1 = __half22float2(*(const __half2*)&v.y);
                t0.x += a0.x; t0.y += a0.y;
                t1.x += a1.x; t1.y += a1.y;
            }
            *(float4*)(Ss + srow * 36 + sc) = make_float4(t0.x, t0.y, t1.x, t1.y);
        }
        __syncthreads();
#pragma unroll 8
        for (int kk = 0; kk < 32; ++kk) {
            float w[4], sv[4];
#pragma unroll
            for (int v = 0; v < 4; ++v) w[v] = Ws[kk * 128 + tx + 32 * v];
#pragma unroll
            for (int u = 0; u < 4; ++u) sv[u] = Ss[(ty + 8 * u) * 36 + kk];
#pragma unroll
            for (int u = 0; u < 4; ++u)
#pragma unroll
                for (int v = 0; v < 4; ++v)
                    acc[u * 4 + v] = fmaf(sv[u], w[v], acc[u * 4 + v]);
        }
    }
}

__global__ __launch_bounds__(256)
void combine_kernel(const float* __restrict__ edge_weight,
                    const float* __restrict__ edge_bias,
                    float* __restrict__ out) {
    __shared__ float Ws[32 * 128];
    __shared__ float Ss[32 * 36];

    const int tid = threadIdx.x;
    const int tx = tid & 31;
    const int ty = tid >> 5;
    const int R0 = blockIdx.x * 32;

    float accN[16], accE[16];
#pragma unroll
    for (int i = 0; i < 16; ++i) { accN[i] = 0.f; accE[i] = 0.f; }

    accum_block(g_Wd,        g_S,           accN, Ws, Ss, tid, tx, ty, R0);
    accum_block(edge_weight, g_S + PLANE_H, accE, Ws, Ss, tid, tx, ty, R0);

    float b2[4], eb[4];
#pragma unroll
    for (int v = 0; v < 4; ++v) {
        b2[v] = g_b2[tx + 32 * v];
        eb[v] = edge_bias[tx + 32 * v];
    }
#pragma unroll
    for (int u = 0; u < 4; ++u)
#pragma unroll
        for (int v = 0; v < 4; ++v) {
            const int rr = R0 + ty + 8 * u;
            const int c = tx + 32 * v;
            out[(size_t)rr * F + c] =
                fmaxf(accN[u * 4 + v] + b2[v], 0.f) + accE[u * 4 + v] + eb[v];
        }
}

extern "C" void kernel_launch(void* const* d_in, const int* in_sizes, int n_in,
                              void* d_out, int out_size) {
    const float* feats       = (const float*)d_in[0];
    const float* node_adj    = (const float*)d_in[1];
    const float* edge_adj    = (const float*)d_in[2];
    const float* node_weight = (const float*)d_in[3];
    const float* node_bias   = (const float*)d_in[4];
    const float* edge_weight = (const float*)d_in[5];
    const float* edge_bias   = (const float*)d_in[6];
    float* out = (float*)d_out;

    cudaFuncSetAttribute(spmm2_f16, cudaFuncAttributeMaxDynamicSharedMemorySize, SMEM_TOTAL);

    colsum_kernel<<<96, 128>>>(feats);
    wtrans_kernel<<<1, 128>>>(node_weight, node_bias);
    prep_feats<<<dim3(N_NODES / BK, 4), 256>>>(feats);
    spmm2_f16<<<GRID, THREADS, SMEM_TOTAL>>>(node_adj, edge_adj);
    combine_kernel<<<N_NODES / 32, 256>>>(edge_weight, edge_bias, out);
}